// round 1
// baseline (speedup 1.0000x reference)
#include <cuda_runtime.h>
#include <cuda_bf16.h>
#include <math.h>

// Problem dims
#define LSRC 256
#define BATCH 64
#define HID 512
#define GATES 2048     // 4*HID
#define VOCAB 32000
#define TDEC 32

// ---------------- scratch (device globals; no allocation allowed) ----------------
__device__ float g_xproj[(size_t)LSRC * BATCH * GATES];   // 134 MB
__device__ float g_hs[(size_t)LSRC * BATCH * HID];        // 33.5 MB
__device__ float g_hsW[(size_t)LSRC * BATCH * HID];       // 33.5 MB
__device__ float g_hA[BATCH * HID];
__device__ float g_hB[BATCH * HID];
__device__ float g_c[BATCH * HID];
__device__ float g_dA[BATCH * HID];
__device__ float g_dB[BATCH * HID];
__device__ float g_cat[BATCH * 2 * HID];
__device__ float g_att[BATCH * HID];
__device__ int   g_y[BATCH];

__device__ __forceinline__ float sigf(float x) { return 1.0f / (1.0f + expf(-x)); }

// ---------------- init ----------------
__global__ void init_kernel(float* hA, float* c, int* y) {
    int i = blockIdx.x * 256 + threadIdx.x;
    if (i < BATCH * HID) { hA[i] = 0.0f; c[i] = 0.0f; }
    if (i < BATCH) y[i] = 1;  // BOS
}

// ---------------- generic SGEMM: C[M][N] = A @ B^T (+bias1+bias2), B is [N][K] ----------------
// BM=BN=64, BK=16, 256 threads, 4x4 micro-tile. Requires M%64==0, N%64==0, K%16==0.
template<bool GATHER>
__global__ void gemm_nt(const float* __restrict__ A, const int* __restrict__ aidx,
                        const float* __restrict__ B,
                        const float* __restrict__ bias1, const float* __restrict__ bias2,
                        float* __restrict__ C, int M, int N, int K)
{
    __shared__ float As[16][68];
    __shared__ float Bs[16][68];
    __shared__ int ridx[64];
    const int m0 = blockIdx.y * 64, n0 = blockIdx.x * 64;
    const int t = threadIdx.x;
    if (GATHER) {
        if (t < 64) ridx[t] = aidx[m0 + t];
        __syncthreads();
    }
    const int tx = t & 15, ty = t >> 4;
    float acc[4][4] = {};
    const int lm = t >> 2, lk = (t & 3) * 4;
    for (int k0 = 0; k0 < K; k0 += 16) {
        const float* arow = A + (size_t)(GATHER ? ridx[lm] : (m0 + lm)) * K + k0 + lk;
        float4 av = *(const float4*)arow;
        As[lk + 0][lm] = av.x; As[lk + 1][lm] = av.y; As[lk + 2][lm] = av.z; As[lk + 3][lm] = av.w;
        float4 bv = *(const float4*)(B + (size_t)(n0 + lm) * K + k0 + lk);
        Bs[lk + 0][lm] = bv.x; Bs[lk + 1][lm] = bv.y; Bs[lk + 2][lm] = bv.z; Bs[lk + 3][lm] = bv.w;
        __syncthreads();
#pragma unroll
        for (int kk = 0; kk < 16; kk++) {
            float4 a4 = *(const float4*)&As[kk][ty * 4];
            float4 b4 = *(const float4*)&Bs[kk][tx * 4];
            float aa[4] = {a4.x, a4.y, a4.z, a4.w};
            float bb[4] = {b4.x, b4.y, b4.z, b4.w};
#pragma unroll
            for (int i = 0; i < 4; i++)
#pragma unroll
                for (int j = 0; j < 4; j++) acc[i][j] += aa[i] * bb[j];
        }
        __syncthreads();
    }
#pragma unroll
    for (int i = 0; i < 4; i++) {
        int m = m0 + ty * 4 + i;
#pragma unroll
        for (int j = 0; j < 4; j++) {
            int n = n0 + tx * 4 + j;
            float v = acc[i][j];
            if (bias1) v += bias1[n];
            if (bias2) v += bias2[n];
            C[(size_t)m * N + n] = v;
        }
    }
}

// ---------------- generic SGEMM: C[M][N] = A @ B (+bias, opt tanh), B is [K][N] ----------------
template<bool TANH>
__global__ void gemm_nn(const float* __restrict__ A, const float* __restrict__ B,
                        const float* __restrict__ bias,
                        float* __restrict__ C, int M, int N, int K)
{
    __shared__ float As[16][68];
    __shared__ float Bs[16][68];
    const int m0 = blockIdx.y * 64, n0 = blockIdx.x * 64;
    const int t = threadIdx.x;
    const int tx = t & 15, ty = t >> 4;
    float acc[4][4] = {};
    const int lm = t >> 2, lk = (t & 3) * 4;   // A load
    const int bk = t >> 4, bn = (t & 15) * 4;  // B load
    for (int k0 = 0; k0 < K; k0 += 16) {
        float4 av = *(const float4*)(A + (size_t)(m0 + lm) * K + k0 + lk);
        As[lk + 0][lm] = av.x; As[lk + 1][lm] = av.y; As[lk + 2][lm] = av.z; As[lk + 3][lm] = av.w;
        float4 bv = *(const float4*)(B + (size_t)(k0 + bk) * N + n0 + bn);
        *(float4*)&Bs[bk][bn] = bv;
        __syncthreads();
#pragma unroll
        for (int kk = 0; kk < 16; kk++) {
            float4 a4 = *(const float4*)&As[kk][ty * 4];
            float4 b4 = *(const float4*)&Bs[kk][tx * 4];
            float aa[4] = {a4.x, a4.y, a4.z, a4.w};
            float bb[4] = {b4.x, b4.y, b4.z, b4.w};
#pragma unroll
            for (int i = 0; i < 4; i++)
#pragma unroll
                for (int j = 0; j < 4; j++) acc[i][j] += aa[i] * bb[j];
        }
        __syncthreads();
    }
#pragma unroll
    for (int i = 0; i < 4; i++) {
        int m = m0 + ty * 4 + i;
#pragma unroll
        for (int j = 0; j < 4; j++) {
            int n = n0 + tx * 4 + j;
            float v = acc[i][j];
            if (bias) v += bias[n];
            if (TANH) v = tanhf(v);
            C[(size_t)m * N + n] = v;
        }
    }
}

// ---------------- encoder step: gates = xproj[t] + h@Whh^T, fused LSTM cell ----------------
// grid = 128 blocks (4 h-cols each => 16 gate cols), 128 threads.
__global__ void enc_step(const float* __restrict__ h_in, float* __restrict__ h_out,
                         float* __restrict__ c, const float* __restrict__ xproj_t,
                         const float* __restrict__ Whh, float* __restrict__ hs_t,
                         const int* __restrict__ src_t)
{
    __shared__ float As[16][68];  // [kk][b]
    __shared__ float Bs[16][20];  // [kk][n_local]
    __shared__ float sg[64][17];  // gates
    const int t = threadIdx.x;
    const int bn = blockIdx.x;           // h-col block: j0 = bn*4
    const int tx = t & 7, ty = t >> 3;   // 8 col-pairs x 16 batch-quads
    float acc[4][2] = {};
    for (int k0 = 0; k0 < 512; k0 += 16) {
#pragma unroll
        for (int r = 0; r < 2; r++) {
            int idx4 = t + r * 128;
            int m = idx4 >> 2, kk = (idx4 & 3) * 4;
            float4 av = *(const float4*)(h_in + m * 512 + k0 + kk);
            As[kk + 0][m] = av.x; As[kk + 1][m] = av.y; As[kk + 2][m] = av.z; As[kk + 3][m] = av.w;
        }
        if (t < 64) {
            int n = t >> 2, kk = (t & 3) * 4;
            int q = n >> 2, jj = n & 3;
            int gcol = q * 512 + bn * 4 + jj;
            float4 bv = *(const float4*)(Whh + (size_t)gcol * 512 + k0 + kk);
            Bs[kk + 0][n] = bv.x; Bs[kk + 1][n] = bv.y; Bs[kk + 2][n] = bv.z; Bs[kk + 3][n] = bv.w;
        }
        __syncthreads();
#pragma unroll
        for (int kk = 0; kk < 16; kk++) {
            float4 a = *(const float4*)&As[kk][ty * 4];
            float b0v = Bs[kk][tx * 2], b1v = Bs[kk][tx * 2 + 1];
            acc[0][0] += a.x * b0v; acc[0][1] += a.x * b1v;
            acc[1][0] += a.y * b0v; acc[1][1] += a.y * b1v;
            acc[2][0] += a.z * b0v; acc[2][1] += a.z * b1v;
            acc[3][0] += a.w * b0v; acc[3][1] += a.w * b1v;
        }
        __syncthreads();
    }
#pragma unroll
    for (int i = 0; i < 4; i++)
#pragma unroll
        for (int j = 0; j < 2; j++) {
            int b = ty * 4 + i, n = tx * 2 + j;
            int q = n >> 2, jj = n & 3;
            int gcol = q * 512 + bn * 4 + jj;
            sg[b][n] = acc[i][j] + xproj_t[b * 2048 + gcol];
        }
    __syncthreads();
#pragma unroll
    for (int r = 0; r < 2; r++) {
        int id = t + r * 128;
        int b = id >> 2, jj = id & 3;
        int j = bn * 4 + jj;
        float gi = sg[b][jj], gf = sg[b][4 + jj], gg = sg[b][8 + jj], go = sg[b][12 + jj];
        float cold = c[b * 512 + j];
        float cn = sigf(gf) * cold + sigf(gi) * tanhf(gg);
        float hn = sigf(go) * tanhf(cn);
        float m = (src_t[b] > 0) ? 1.0f : 0.0f;
        h_out[b * 512 + j] = m * hn + (1.0f - m) * h_in[b * 512 + j];
        c[b * 512 + j] = m * cn + (1.0f - m) * cold;
        hs_t[b * 512 + j] = hn * m;
    }
}

// ---------------- decoder LSTM step: gates = emb[y]@Wih^T + hd@Whh^T + b, fused cell ----------------
__global__ void dec_step(const float* __restrict__ h_in, float* __restrict__ h_out,
                         float* __restrict__ c,
                         const float* __restrict__ emb, const int* __restrict__ y,
                         const float* __restrict__ Wih, const float* __restrict__ Whh,
                         const float* __restrict__ bih, const float* __restrict__ bhh)
{
    __shared__ float As[16][68];
    __shared__ float Bs[16][20];
    __shared__ float sg[64][17];
    __shared__ int ytok[64];
    const int t = threadIdx.x;
    const int bn = blockIdx.x;
    if (t < 64) ytok[t] = y[t];
    __syncthreads();
    const int tx = t & 7, ty = t >> 3;
    float acc[4][2] = {};
    for (int p = 0; p < 2; p++) {
        const float* W = p ? Whh : Wih;
        for (int k0 = 0; k0 < 512; k0 += 16) {
#pragma unroll
            for (int r = 0; r < 2; r++) {
                int idx4 = t + r * 128;
                int m = idx4 >> 2, kk = (idx4 & 3) * 4;
                const float* arow = p ? (h_in + m * 512) : (emb + (size_t)ytok[m] * 512);
                float4 av = *(const float4*)(arow + k0 + kk);
                As[kk + 0][m] = av.x; As[kk + 1][m] = av.y; As[kk + 2][m] = av.z; As[kk + 3][m] = av.w;
            }
            if (t < 64) {
                int n = t >> 2, kk = (t & 3) * 4;
                int q = n >> 2, jj = n & 3;
                int gcol = q * 512 + bn * 4 + jj;
                float4 bv = *(const float4*)(W + (size_t)gcol * 512 + k0 + kk);
                Bs[kk + 0][n] = bv.x; Bs[kk + 1][n] = bv.y; Bs[kk + 2][n] = bv.z; Bs[kk + 3][n] = bv.w;
            }
            __syncthreads();
#pragma unroll
            for (int kk = 0; kk < 16; kk++) {
                float4 a = *(const float4*)&As[kk][ty * 4];
                float b0v = Bs[kk][tx * 2], b1v = Bs[kk][tx * 2 + 1];
                acc[0][0] += a.x * b0v; acc[0][1] += a.x * b1v;
                acc[1][0] += a.y * b0v; acc[1][1] += a.y * b1v;
                acc[2][0] += a.z * b0v; acc[2][1] += a.z * b1v;
                acc[3][0] += a.w * b0v; acc[3][1] += a.w * b1v;
            }
            __syncthreads();
        }
    }
#pragma unroll
    for (int i = 0; i < 4; i++)
#pragma unroll
        for (int j = 0; j < 2; j++) {
            int b = ty * 4 + i, n = tx * 2 + j;
            int q = n >> 2, jj = n & 3;
            int gcol = q * 512 + bn * 4 + jj;
            sg[b][n] = acc[i][j] + bih[gcol] + bhh[gcol];
        }
    __syncthreads();
#pragma unroll
    for (int r = 0; r < 2; r++) {
        int id = t + r * 128;
        int b = id >> 2, jj = id & 3;
        int j = bn * 4 + jj;
        float gi = sg[b][jj], gf = sg[b][4 + jj], gg = sg[b][8 + jj], go = sg[b][12 + jj];
        float cold = c[b * 512 + j];
        float cn = sigf(gf) * cold + sigf(gi) * tanhf(gg);
        float hn = sigf(go) * tanhf(cn);
        h_out[b * 512 + j] = hn;
        c[b * 512 + j] = cn;
    }
}

// ---------------- attention: scores + softmax + ctx, writes cat=[ctx, hd] ----------------
// grid = 64 (one block per batch elem), 256 threads.
__global__ void attn_kernel(const float* __restrict__ hd, const float* __restrict__ hsW,
                            const float* __restrict__ hs, const int* __restrict__ source,
                            float* __restrict__ cat)
{
    __shared__ float hds[512];
    __shared__ float sc[256];
    __shared__ float red[16];
    const int b = blockIdx.x, t = threadIdx.x;
    hds[t] = hd[b * 512 + t];
    hds[t + 256] = hd[b * 512 + 256 + t];
    __syncthreads();
    const int w = t >> 5, lane = t & 31;
    for (int l = w; l < 256; l += 8) {
        const float* hw = hsW + ((size_t)l * 64 + b) * 512;
        float s = 0.0f;
#pragma unroll
        for (int kk = 0; kk < 16; kk++) s += hds[lane + kk * 32] * hw[lane + kk * 32];
#pragma unroll
        for (int o = 16; o; o >>= 1) s += __shfl_xor_sync(0xffffffffu, s, o);
        if (lane == 0) sc[l] = s;
    }
    __syncthreads();
    float myscore = sc[t];
    float v = myscore;
#pragma unroll
    for (int o = 16; o; o >>= 1) v = fmaxf(v, __shfl_xor_sync(0xffffffffu, v, o));
    if (lane == 0) red[w] = v;
    __syncthreads();
    float mx = red[0];
#pragma unroll
    for (int i = 1; i < 8; i++) mx = fmaxf(mx, red[i]);
    float ev = expf(myscore - mx) * (source[t * 64 + b] > 0 ? 1.0f : 0.0f);
    sc[t] = ev;  // each thread writes only its own slot
    float sv = ev;
#pragma unroll
    for (int o = 16; o; o >>= 1) sv += __shfl_xor_sync(0xffffffffu, sv, o);
    if (lane == 0) red[8 + w] = sv;
    __syncthreads();
    float tot = 0.0f;
#pragma unroll
    for (int i = 0; i < 8; i++) tot += red[8 + i];
    float inv = 1.0f / tot;
    for (int hcol = t; hcol < 512; hcol += 256) {
        float a = 0.0f;
        for (int l = 0; l < 256; l++) a += sc[l] * hs[((size_t)l * 64 + b) * 512 + hcol];
        cat[b * 1024 + hcol] = a * inv;
        cat[b * 1024 + 512 + hcol] = hds[hcol];
    }
}

// ---------------- att = tanh(cat @ W_c + b_c), grid=128 (4 cols each), 128 threads ----------------
__global__ void att_kernel(const float* __restrict__ cat, const float* __restrict__ Wc,
                           const float* __restrict__ bc, float* __restrict__ att)
{
    __shared__ float As[16][68];
    __shared__ float Bs[16][8];
    const int t = threadIdx.x;
    const int n0 = blockIdx.x * 4;
    const int tx = t & 3, ty = t >> 2;  // col, batch-pair
    float acc0 = 0.0f, acc1 = 0.0f;
    for (int k0 = 0; k0 < 1024; k0 += 16) {
#pragma unroll
        for (int r = 0; r < 2; r++) {
            int idx4 = t + r * 128;
            int m = idx4 >> 2, kk = (idx4 & 3) * 4;
            float4 av = *(const float4*)(cat + m * 1024 + k0 + kk);
            As[kk + 0][m] = av.x; As[kk + 1][m] = av.y; As[kk + 2][m] = av.z; As[kk + 3][m] = av.w;
        }
        if (t < 64) {
            int kk = t >> 2, n = t & 3;
            Bs[kk][n] = Wc[(size_t)(k0 + kk) * 512 + n0 + n];
        }
        __syncthreads();
#pragma unroll
        for (int kk = 0; kk < 16; kk++) {
            float bv = Bs[kk][tx];
            acc0 += As[kk][ty * 2] * bv;
            acc1 += As[kk][ty * 2 + 1] * bv;
        }
        __syncthreads();
    }
    int b0 = ty * 2;
    att[b0 * 512 + n0 + tx] = tanhf(acc0 + bc[n0 + tx]);
    att[(b0 + 1) * 512 + n0 + tx] = tanhf(acc1 + bc[n0 + tx]);
}

// ---------------- argmax over 32000 logits per batch row (first-max tie-break) ----------------
__global__ void argmax_kernel(const float* __restrict__ logits, int* __restrict__ y)
{
    const int b = blockIdx.x, t = threadIdx.x;
    const float* row = logits + (size_t)b * VOCAB;
    float best = -3.402823466e38f;
    int bi = 0x7fffffff;
    for (int i = t; i < VOCAB; i += 256) {
        float vv = row[i];
        if (vv > best) { best = vv; bi = i; }
    }
    __shared__ float bv[256];
    __shared__ int bix[256];
    bv[t] = best; bix[t] = bi;
    __syncthreads();
    for (int s = 128; s; s >>= 1) {
        if (t < s) {
            if (bv[t + s] > bv[t] || (bv[t + s] == bv[t] && bix[t + s] < bix[t])) {
                bv[t] = bv[t + s];
                bix[t] = bix[t + s];
            }
        }
        __syncthreads();
    }
    if (t == 0) y[b] = bix[0];
}

// ---------------- host launch ----------------
extern "C" void kernel_launch(void* const* d_in, const int* in_sizes, int n_in,
                              void* d_out, int out_size)
{
    const int*   src     = (const int*)d_in[0];
    const float* enc_emb = (const float*)d_in[1];
    const float* enc_Wih = (const float*)d_in[2];
    const float* enc_Whh = (const float*)d_in[3];
    const float* enc_bih = (const float*)d_in[4];
    const float* enc_bhh = (const float*)d_in[5];
    const float* dec_emb = (const float*)d_in[6];
    const float* dec_Wih = (const float*)d_in[7];
    const float* dec_Whh = (const float*)d_in[8];
    const float* dec_bih = (const float*)d_in[9];
    const float* dec_bhh = (const float*)d_in[10];
    const float* W_a     = (const float*)d_in[11];
    const float* W_c     = (const float*)d_in[12];
    const float* b_c     = (const float*)d_in[13];
    const float* out_W   = (const float*)d_in[14];
    const float* out_b   = (const float*)d_in[15];
    float* out = (float*)d_out;

    float *xproj, *hs, *hsW, *hA, *hB, *c, *dA, *dB, *cat, *att;
    int* y;
    cudaGetSymbolAddress((void**)&xproj, g_xproj);
    cudaGetSymbolAddress((void**)&hs, g_hs);
    cudaGetSymbolAddress((void**)&hsW, g_hsW);
    cudaGetSymbolAddress((void**)&hA, g_hA);
    cudaGetSymbolAddress((void**)&hB, g_hB);
    cudaGetSymbolAddress((void**)&c, g_c);
    cudaGetSymbolAddress((void**)&dA, g_dA);
    cudaGetSymbolAddress((void**)&dB, g_dB);
    cudaGetSymbolAddress((void**)&cat, g_cat);
    cudaGetSymbolAddress((void**)&att, g_att);
    cudaGetSymbolAddress((void**)&y, g_y);

    init_kernel<<<128, 256>>>(hA, c, y);

    // xproj = emb[source] @ enc_Wih^T + (bih + bhh)   [16384 x 2048, K=512]
    gemm_nt<true><<<dim3(GATES / 64, (LSRC * BATCH) / 64), 256>>>(
        enc_emb, src, enc_Wih, enc_bih, enc_bhh, xproj, LSRC * BATCH, GATES, HID);

    // encoder recurrence (double-buffered h)
    for (int t = 0; t < LSRC; t++) {
        const float* hin = (t & 1) ? hB : hA;
        float* hout = (t & 1) ? hA : hB;
        enc_step<<<128, 128>>>(hin, hout, c,
                               xproj + (size_t)t * BATCH * GATES,
                               enc_Whh,
                               hs + (size_t)t * BATCH * HID,
                               src + t * BATCH);
    }
    // final encoder state: h in hA (t=255 odd writes hA), c in g_c

    // hsW = hs @ W_a   [16384 x 512, K=512]
    gemm_nn<false><<<dim3(HID / 64, (LSRC * BATCH) / 64), 256>>>(
        hs, W_a, nullptr, hsW, LSRC * BATCH, HID, HID);

    for (int t = 0; t < TDEC; t++) {
        const float* hin = (t == 0) ? hA : ((t & 1) ? dA : dB);
        float* hout = (t & 1) ? dB : dA;
        dec_step<<<128, 128>>>(hin, hout, c, dec_emb, y,
                               dec_Wih, dec_Whh, dec_bih, dec_bhh);
        attn_kernel<<<64, 256>>>(hout, hsW, hs, src, cat);
        att_kernel<<<128, 128>>>(cat, W_c, b_c, att);
        gemm_nt<false><<<dim3(VOCAB / 64, 1), 256>>>(
            att, nullptr, out_W, out_b, nullptr,
            out + (size_t)t * BATCH * VOCAB, BATCH, VOCAB, HID);
        argmax_kernel<<<64, 256>>>(out + (size_t)t * BATCH * VOCAB, y);
    }
}

// round 2
// speedup vs baseline: 1.1297x; 1.1297x over previous
#include <cuda_runtime.h>
#include <cuda_bf16.h>
#include <math.h>
#include <float.h>

// Problem dims
#define LSRC 256
#define BATCH 64
#define HID 512
#define GATES 2048     // 4*HID
#define VOCAB 32000
#define TDEC 32
#define MAXGRID 160

// ---------------- scratch (device globals; no allocation allowed) ----------------
__device__ float g_xproj[(size_t)LSRC * BATCH * GATES];   // 134 MB
__device__ float g_hs[(size_t)LSRC * BATCH * HID];        // 33.5 MB
__device__ float g_hsW[(size_t)LSRC * BATCH * HID];       // 33.5 MB
__device__ float g_hT0[HID * BATCH];   // transposed h [k][b]
__device__ float g_hT1[HID * BATCH];
__device__ float g_cT[HID * BATCH];    // transposed c [j][b]
__device__ float g_dT0[HID * BATCH];
__device__ float g_dT1[HID * BATCH];
__device__ float g_hdrow[BATCH * HID];
__device__ float g_xT[HID * BATCH];    // decoder input emb, transposed
__device__ float g_ctxT[HID * BATCH];
__device__ float g_attT[HID * BATCH];
__device__ float g_partV[MAXGRID * BATCH];
__device__ int   g_partI[MAXGRID * BATCH];
__device__ unsigned g_cnt = 0;
__device__ unsigned g_gen = 0;

__device__ __forceinline__ float sigf(float x) { return 1.0f / (1.0f + expf(-x)); }

// ---------------- grid barrier (all blocks co-resident by construction) ----------------
__device__ __forceinline__ void gridbar(unsigned nb, unsigned& mygen) {
    __syncthreads();
    if (threadIdx.x == 0) {
        __threadfence();
        unsigned a = atomicAdd(&g_cnt, 1u);
        if (a == nb - 1u) {
            g_cnt = 0u;
            __threadfence();
            atomicAdd(&g_gen, 1u);
        } else {
            while (atomicAdd(&g_gen, 0u) == mygen) { __nanosleep(64); }
        }
        mygen++;
    }
    __syncthreads();
}

// ---------------- init ----------------
__global__ void init_kernel(float* hT0, float* cT) {
    int i = blockIdx.x * 256 + threadIdx.x;   // 128*256 = 32768 = HID*BATCH
    hT0[i] = 0.0f;
    cT[i] = 0.0f;
}

// ---------------- SGEMM: C[M][N] = A @ B^T (+bias1+bias2), B is [N][K] ----------------
template<bool GATHER>
__global__ void gemm_nt(const float* __restrict__ A, const int* __restrict__ aidx,
                        const float* __restrict__ B,
                        const float* __restrict__ bias1, const float* __restrict__ bias2,
                        float* __restrict__ C, int M, int N, int K)
{
    __shared__ float As[16][68];
    __shared__ float Bs[16][68];
    __shared__ int ridx[64];
    const int m0 = blockIdx.y * 64, n0 = blockIdx.x * 64;
    const int t = threadIdx.x;
    if (GATHER) {
        if (t < 64) ridx[t] = aidx[m0 + t];
        __syncthreads();
    }
    const int tx = t & 15, ty = t >> 4;
    float acc[4][4] = {};
    const int lm = t >> 2, lk = (t & 3) * 4;
    for (int k0 = 0; k0 < K; k0 += 16) {
        const float* arow = A + (size_t)(GATHER ? ridx[lm] : (m0 + lm)) * K + k0 + lk;
        float4 av = *(const float4*)arow;
        As[lk + 0][lm] = av.x; As[lk + 1][lm] = av.y; As[lk + 2][lm] = av.z; As[lk + 3][lm] = av.w;
        float4 bv = *(const float4*)(B + (size_t)(n0 + lm) * K + k0 + lk);
        Bs[lk + 0][lm] = bv.x; Bs[lk + 1][lm] = bv.y; Bs[lk + 2][lm] = bv.z; Bs[lk + 3][lm] = bv.w;
        __syncthreads();
#pragma unroll
        for (int kk = 0; kk < 16; kk++) {
            float4 a4 = *(const float4*)&As[kk][ty * 4];
            float4 b4 = *(const float4*)&Bs[kk][tx * 4];
            float aa[4] = {a4.x, a4.y, a4.z, a4.w};
            float bb[4] = {b4.x, b4.y, b4.z, b4.w};
#pragma unroll
            for (int i = 0; i < 4; i++)
#pragma unroll
                for (int j = 0; j < 4; j++) acc[i][j] += aa[i] * bb[j];
        }
        __syncthreads();
    }
#pragma unroll
    for (int i = 0; i < 4; i++) {
        int m = m0 + ty * 4 + i;
#pragma unroll
        for (int j = 0; j < 4; j++) {
            int n = n0 + tx * 4 + j;
            float v = acc[i][j];
            if (bias1) v += bias1[n];
            if (bias2) v += bias2[n];
            C[(size_t)m * N + n] = v;
        }
    }
}

// ---------------- SGEMM: C[M][N] = A @ B, B is [K][N] ----------------
__global__ void gemm_nn(const float* __restrict__ A, const float* __restrict__ B,
                        float* __restrict__ C, int M, int N, int K)
{
    __shared__ float As[16][68];
    __shared__ float Bs[16][68];
    const int m0 = blockIdx.y * 64, n0 = blockIdx.x * 64;
    const int t = threadIdx.x;
    const int tx = t & 15, ty = t >> 4;
    float acc[4][4] = {};
    const int lm = t >> 2, lk = (t & 3) * 4;
    const int bk = t >> 4, bn = (t & 15) * 4;
    for (int k0 = 0; k0 < K; k0 += 16) {
        float4 av = *(const float4*)(A + (size_t)(m0 + lm) * K + k0 + lk);
        As[lk + 0][lm] = av.x; As[lk + 1][lm] = av.y; As[lk + 2][lm] = av.z; As[lk + 3][lm] = av.w;
        float4 bv = *(const float4*)(B + (size_t)(k0 + bk) * N + n0 + bn);
        *(float4*)&Bs[bk][bn] = bv;
        __syncthreads();
#pragma unroll
        for (int kk = 0; kk < 16; kk++) {
            float4 a4 = *(const float4*)&As[kk][ty * 4];
            float4 b4 = *(const float4*)&Bs[kk][tx * 4];
            float aa[4] = {a4.x, a4.y, a4.z, a4.w};
            float bb[4] = {b4.x, b4.y, b4.z, b4.w};
#pragma unroll
            for (int i = 0; i < 4; i++)
#pragma unroll
                for (int j = 0; j < 4; j++) acc[i][j] += aa[i] * bb[j];
        }
        __syncthreads();
    }
#pragma unroll
    for (int i = 0; i < 4; i++) {
        int m = m0 + ty * 4 + i;
#pragma unroll
        for (int j = 0; j < 4; j++)
            C[(size_t)m * N + (n0 + tx * 4 + j)] = acc[i][j];
    }
}

// ---------------- persistent encoder: 128 blocks, 256 steps, 1 barrier/step ----------------
// Block bn owns 4 h-cols (j = bn*4+jj) => 16 gate cols. Whh slice resident in smem.
__global__ __launch_bounds__(256, 1) void enc_persist(
    const float* __restrict__ xproj, const float* __restrict__ Whh,
    const int* __restrict__ src,
    float* __restrict__ hT0, float* __restrict__ hT1,
    float* __restrict__ cT, float* __restrict__ hs)
{
    __shared__ float wsm[512 * 16];    // [k][col16]
    __shared__ float sg[64][17];
    const int t = threadIdx.x, bn = blockIdx.x;
    unsigned mygen = 0;
    if (t == 0) mygen = atomicAdd(&g_gen, 0u);

    for (int i = t; i < 512 * 16; i += 256) {
        int col16 = i >> 9, k = i & 511;
        int q = col16 >> 2, jj = col16 & 3;
        wsm[k * 16 + col16] = Whh[(size_t)(q * 512 + bn * 4 + jj) * 512 + k];
    }
    __syncthreads();

    const int col16 = t & 15, b0 = (t >> 4) * 4;
    const int q = col16 >> 2, jj0 = col16 & 3;
    const int gcol = q * 512 + bn * 4 + jj0;

    for (int tt = 0; tt < LSRC; tt++) {
        const float* hin = (tt & 1) ? hT1 : hT0;
        float* hout = (tt & 1) ? hT0 : hT1;
        float a0 = 0.f, a1 = 0.f, a2 = 0.f, a3 = 0.f;
        for (int k = 0; k < 512; k += 4) {
#pragma unroll
            for (int u = 0; u < 4; u++) {
                float w = wsm[(k + u) * 16 + col16];
                float4 hv = *(const float4*)(hin + (k + u) * 64 + b0);
                a0 += hv.x * w; a1 += hv.y * w; a2 += hv.z * w; a3 += hv.w * w;
            }
        }
        const float* xp = xproj + (size_t)tt * 64 * 2048;
        sg[b0 + 0][col16] = a0 + xp[(b0 + 0) * 2048 + gcol];
        sg[b0 + 1][col16] = a1 + xp[(b0 + 1) * 2048 + gcol];
        sg[b0 + 2][col16] = a2 + xp[(b0 + 2) * 2048 + gcol];
        sg[b0 + 3][col16] = a3 + xp[(b0 + 3) * 2048 + gcol];
        __syncthreads();
        {
            int b = t >> 2, jj = t & 3;
            int j = bn * 4 + jj;
            float gi = sg[b][jj], gf = sg[b][4 + jj], gg = sg[b][8 + jj], go = sg[b][12 + jj];
            float cold = cT[j * 64 + b];
            float cn = sigf(gf) * cold + sigf(gi) * tanhf(gg);
            float hn = sigf(go) * tanhf(cn);
            float m = (src[tt * 64 + b] > 0) ? 1.0f : 0.0f;
            hout[j * 64 + b] = m * hn + (1.0f - m) * hin[j * 64 + b];
            cT[j * 64 + b] = m * cn + (1.0f - m) * cold;
            hs[((size_t)tt * 64 + b) * 512 + j] = hn * m;
        }
        gridbar(gridDim.x, mygen);
    }
}

// ---------------- persistent decoder: all 32 steps in one kernel ----------------
// dyn smem: wih[8192] | whh[8192] | bsum[16] | pool[4704]
#define DEC_POOL_OFF 16400
#define DEC_SMEM_FLOATS (16400 + 4704)

__global__ __launch_bounds__(256, 1) void dec_persist(
    const float* __restrict__ dec_emb,
    const float* __restrict__ Wih, const float* __restrict__ Whh,
    const float* __restrict__ bih, const float* __restrict__ bhh,
    const float* __restrict__ Wc, const float* __restrict__ bc,
    const float* __restrict__ outW, const float* __restrict__ outb,
    const float* __restrict__ hsW, const float* __restrict__ hs,
    const int* __restrict__ src,
    const float* __restrict__ encH,
    float* __restrict__ dT0, float* __restrict__ dT1, float* __restrict__ cT,
    float* __restrict__ hdrow, float* __restrict__ xT,
    float* __restrict__ ctxT, float* __restrict__ attT,
    float* __restrict__ partV, int* __restrict__ partI,
    float* __restrict__ out)
{
    extern __shared__ float dyn[];
    float* wih_s = dyn;
    float* whh_s = dyn + 8192;
    float* bsum = dyn + 16384;
    float* pool = dyn + DEC_POOL_OFF;

    const int t = threadIdx.x, bid = blockIdx.x;
    const unsigned gd = gridDim.x;
    unsigned mygen = 0;
    if (t == 0) mygen = atomicAdd(&g_gen, 0u);

    const int col16 = t & 15, b0 = (t >> 4) * 4;
    const int q = col16 >> 2, jj0 = col16 & 3;
    const int gcol = q * 512 + bid * 4 + jj0;  // valid for bid<128

    if (bid < 128) {
        for (int i = t; i < 512 * 16; i += 256) {
            int c16 = i >> 9, k = i & 511;
            int qq = c16 >> 2, jj = c16 & 3;
            int gc = qq * 512 + bid * 4 + jj;
            wih_s[k * 16 + c16] = Wih[(size_t)gc * 512 + k];
            whh_s[k * 16 + c16] = Whh[(size_t)gc * 512 + k];
        }
        if (t < 16) {
            int qq = t >> 2, jj = t & 3;
            int gc = qq * 512 + bid * 4 + jj;
            bsum[t] = bih[gc] + bhh[gc];
        }
    }
    // pre-gather BOS embedding into xT
    if (bid < 64) {
        xT[t * 64 + bid] = dec_emb[512 + t];               // row BOS=1
        xT[(t + 256) * 64 + bid] = dec_emb[512 + 256 + t];
    }
    gridbar(gd, mygen);

    for (int s = 0; s < TDEC; s++) {
        const float* hdin = (s == 0) ? encH : ((s & 1) ? dT1 : dT0);
        float* hdout = (s & 1) ? dT0 : dT1;

        // ---- phase A: decoder LSTM cell ----
        if (bid < 128) {
            float* sg = pool;  // [64][17]
            float a0 = 0.f, a1 = 0.f, a2 = 0.f, a3 = 0.f;
            for (int k = 0; k < 512; k += 4) {
#pragma unroll
                for (int u = 0; u < 4; u++) {
                    float w = wih_s[(k + u) * 16 + col16];
                    float4 xv = *(const float4*)(xT + (k + u) * 64 + b0);
                    a0 += xv.x * w; a1 += xv.y * w; a2 += xv.z * w; a3 += xv.w * w;
                }
            }
            for (int k = 0; k < 512; k += 4) {
#pragma unroll
                for (int u = 0; u < 4; u++) {
                    float w = whh_s[(k + u) * 16 + col16];
                    float4 hv = *(const float4*)(hdin + (k + u) * 64 + b0);
                    a0 += hv.x * w; a1 += hv.y * w; a2 += hv.z * w; a3 += hv.w * w;
                }
            }
            float bs = bsum[col16];
            sg[(b0 + 0) * 17 + col16] = a0 + bs;
            sg[(b0 + 1) * 17 + col16] = a1 + bs;
            sg[(b0 + 2) * 17 + col16] = a2 + bs;
            sg[(b0 + 3) * 17 + col16] = a3 + bs;
            __syncthreads();
            {
                int b = t >> 2, jj = t & 3;
                int j = bid * 4 + jj;
                float gi = sg[b * 17 + jj], gf = sg[b * 17 + 4 + jj];
                float gg = sg[b * 17 + 8 + jj], go = sg[b * 17 + 12 + jj];
                float cold = cT[j * 64 + b];
                float cn = sigf(gf) * cold + sigf(gi) * tanhf(gg);
                float hn = sigf(go) * tanhf(cn);
                hdout[j * 64 + b] = hn;
                hdrow[b * 512 + j] = hn;
                cT[j * 64 + b] = cn;
            }
        }
        gridbar(gd, mygen);

        // ---- phase B: attention scores + softmax + context (block = batch) ----
        if (bid < 64) {
            float* hd_sm = pool;          // 512
            float* sc = pool + 512;       // 256
            float* red = pool + 768;      // 16
            hd_sm[t] = hdrow[bid * 512 + t];
            hd_sm[t + 256] = hdrow[bid * 512 + 256 + t];
            __syncthreads();
            const int w = t >> 5, lane = t & 31;
            for (int l = w; l < 256; l += 8) {
                const float* hw = hsW + ((size_t)l * 64 + bid) * 512;
                float sv = 0.0f;
#pragma unroll
                for (int kk = 0; kk < 16; kk++) sv += hd_sm[lane + kk * 32] * hw[lane + kk * 32];
#pragma unroll
                for (int o = 16; o; o >>= 1) sv += __shfl_xor_sync(0xffffffffu, sv, o);
                if (lane == 0) sc[l] = sv;
            }
            __syncthreads();
            float my = sc[t];
            float v = my;
#pragma unroll
            for (int o = 16; o; o >>= 1) v = fmaxf(v, __shfl_xor_sync(0xffffffffu, v, o));
            if (lane == 0) red[w] = v;
            __syncthreads();
            float mx = red[0];
#pragma unroll
            for (int i = 1; i < 8; i++) mx = fmaxf(mx, red[i]);
            float ev = expf(my - mx) * (src[t * 64 + bid] > 0 ? 1.0f : 0.0f);
            sc[t] = ev;
            float sv = ev;
#pragma unroll
            for (int o = 16; o; o >>= 1) sv += __shfl_xor_sync(0xffffffffu, sv, o);
            if (lane == 0) red[8 + w] = sv;
            __syncthreads();
            float tot = 0.0f;
#pragma unroll
            for (int i = 0; i < 8; i++) tot += red[8 + i];
            float inv = 1.0f / tot;
            for (int hcol = t; hcol < 512; hcol += 256) {
                float a = 0.0f;
                for (int l = 0; l < 256; l++) a += sc[l] * hs[((size_t)l * 64 + bid) * 512 + hcol];
                ctxT[hcol * 64 + bid] = a * inv;
            }
        }
        gridbar(gd, mygen);

        // ---- phase C: attT = tanh(cat @ Wc + bc), cat = [ctxT ; hdout] ----
        if (bid < 128) {
            float* As = pool;            // [64][68]
            float* Ws = pool + 64 * 68;  // [64][4]
            const int col = t & 3, brow = t >> 2;
            float acc = 0.0f;
            for (int kc = 0; kc < 16; kc++) {
                __syncthreads();
#pragma unroll
                for (int r = 0; r < 4; r++) {
                    int idx4 = t + r * 256;
                    int row = idx4 >> 4, b4 = (idx4 & 15) * 4;
                    int k = kc * 64 + row;
                    const float* sp = (k < 512) ? (ctxT + (size_t)k * 64)
                                                : (hdout + (size_t)(k - 512) * 64);
                    *(float4*)&As[row * 68 + b4] = *(const float4*)(sp + b4);
                }
                {
                    int kk = t >> 2, c = t & 3;
                    Ws[kk * 4 + c] = Wc[(size_t)(kc * 64 + kk) * 512 + bid * 4 + c];
                }
                __syncthreads();
#pragma unroll 8
                for (int kk = 0; kk < 64; kk++)
                    acc += As[kk * 68 + brow] * Ws[kk * 4 + col];
            }
            attT[(bid * 4 + col) * 64 + brow] = tanhf(acc + bc[bid * 4 + col]);
        }
        gridbar(gd, mygen);

        // ---- phase D: logits = attT^T @ outW^T + outb, fused argmax partials ----
        {
            float* As = pool;              // [16][68] (row=k, col=b)
            float* Bs = pool + 16 * 68;    // [16][68] (row=k, col=n)
            const int tx = t & 15, ty = t >> 4;
            float bestv[4];
            int besti[4];
#pragma unroll
            for (int i = 0; i < 4; i++) { bestv[i] = -FLT_MAX; besti[i] = 0x7fffffff; }
            for (int tile = bid; tile < VOCAB / 64; tile += gd) {
                const int n0 = tile * 64;
                float acc[4][4] = {};
                for (int k0 = 0; k0 < 512; k0 += 16) {
                    __syncthreads();
                    {
                        int row = t >> 4, b4 = (t & 15) * 4;
                        *(float4*)&As[row * 68 + b4] =
                            *(const float4*)(attT + (size_t)(k0 + row) * 64 + b4);
                    }
                    {
                        int n = t >> 2, kg = (t & 3) * 4;
                        float4 wv = *(const float4*)(outW + (size_t)(n0 + n) * 512 + k0 + kg);
                        Bs[(kg + 0) * 68 + n] = wv.x; Bs[(kg + 1) * 68 + n] = wv.y;
                        Bs[(kg + 2) * 68 + n] = wv.z; Bs[(kg + 3) * 68 + n] = wv.w;
                    }
                    __syncthreads();
#pragma unroll
                    for (int kk = 0; kk < 16; kk++) {
                        float4 a4 = *(const float4*)&As[kk * 68 + ty * 4];
                        float4 b4v = *(const float4*)&Bs[kk * 68 + tx * 4];
                        float aa[4] = {a4.x, a4.y, a4.z, a4.w};
                        float bb[4] = {b4v.x, b4v.y, b4v.z, b4v.w};
#pragma unroll
                        for (int i = 0; i < 4; i++)
#pragma unroll
                            for (int j = 0; j < 4; j++) acc[i][j] += aa[i] * bb[j];
                    }
                }
#pragma unroll
                for (int i = 0; i < 4; i++) {
                    int b = ty * 4 + i;
#pragma unroll
                    for (int j = 0; j < 4; j++) {
                        int n = n0 + tx * 4 + j;
                        float v = acc[i][j] + outb[n];
                        out[((size_t)s * 64 + b) * VOCAB + n] = v;
                        if (v > bestv[i]) { bestv[i] = v; besti[i] = n; }
                    }
                }
            }
            __syncthreads();
            float* rv = pool + 2176;
            int* ri = (int*)(pool + 3264);
#pragma unroll
            for (int i = 0; i < 4; i++) {
                int b = ty * 4 + i;
                rv[b * 17 + tx] = bestv[i];
                ri[b * 17 + tx] = besti[i];
            }
            __syncthreads();
            if (t < 64) {
                float bv = rv[t * 17]; int bi = ri[t * 17];
#pragma unroll
                for (int x = 1; x < 16; x++) {
                    float v = rv[t * 17 + x]; int ix = ri[t * 17 + x];
                    if (v > bv || (v == bv && ix < bi)) { bv = v; bi = ix; }
                }
                partV[bid * 64 + t] = bv;
                partI[bid * 64 + t] = bi;
            }
        }
        gridbar(gd, mygen);

        // ---- phase E: global argmax + gather next embedding (block = batch) ----
        if (bid < 64) {
            float* ev = pool;
            int* ei = (int*)(pool + 256);
            float bv = -FLT_MAX; int bi = 0x7fffffff;
            for (unsigned g = t; g < gd; g += 256) {
                float v = partV[g * 64 + bid]; int ix = partI[g * 64 + bid];
                if (v > bv || (v == bv && ix < bi)) { bv = v; bi = ix; }
            }
            ev[t] = bv; ei[t] = bi;
            __syncthreads();
            for (int s2 = 128; s2; s2 >>= 1) {
                if (t < s2) {
                    float v = ev[t + s2]; int ix = ei[t + s2];
                    if (v > ev[t] || (v == ev[t] && ix < ei[t])) { ev[t] = v; ei[t] = ix; }
                }
                __syncthreads();
            }
            int ynext = ei[0];
            xT[t * 64 + bid] = dec_emb[(size_t)ynext * 512 + t];
            xT[(t + 256) * 64 + bid] = dec_emb[(size_t)ynext * 512 + 256 + t];
        }
        gridbar(gd, mygen);
    }
}

// ---------------- host launch ----------------
extern "C" void kernel_launch(void* const* d_in, const int* in_sizes, int n_in,
                              void* d_out, int out_size)
{
    const int*   src     = (const int*)d_in[0];
    const float* enc_emb = (const float*)d_in[1];
    const float* enc_Wih = (const float*)d_in[2];
    const float* enc_Whh = (const float*)d_in[3];
    const float* enc_bih = (const float*)d_in[4];
    const float* enc_bhh = (const float*)d_in[5];
    const float* dec_emb = (const float*)d_in[6];
    const float* dec_Wih = (const float*)d_in[7];
    const float* dec_Whh = (const float*)d_in[8];
    const float* dec_bih = (const float*)d_in[9];
    const float* dec_bhh = (const float*)d_in[10];
    const float* W_a     = (const float*)d_in[11];
    const float* W_c     = (const float*)d_in[12];
    const float* b_c     = (const float*)d_in[13];
    const float* out_W   = (const float*)d_in[14];
    const float* out_b   = (const float*)d_in[15];
    float* out = (float*)d_out;

    float *xproj, *hs, *hsW, *hT0, *hT1, *cT, *dT0, *dT1, *hdrow, *xT, *ctxT, *attT, *partV;
    int* partI;
    cudaGetSymbolAddress((void**)&xproj, g_xproj);
    cudaGetSymbolAddress((void**)&hs, g_hs);
    cudaGetSymbolAddress((void**)&hsW, g_hsW);
    cudaGetSymbolAddress((void**)&hT0, g_hT0);
    cudaGetSymbolAddress((void**)&hT1, g_hT1);
    cudaGetSymbolAddress((void**)&cT, g_cT);
    cudaGetSymbolAddress((void**)&dT0, g_dT0);
    cudaGetSymbolAddress((void**)&dT1, g_dT1);
    cudaGetSymbolAddress((void**)&hdrow, g_hdrow);
    cudaGetSymbolAddress((void**)&xT, g_xT);
    cudaGetSymbolAddress((void**)&ctxT, g_ctxT);
    cudaGetSymbolAddress((void**)&attT, g_attT);
    cudaGetSymbolAddress((void**)&partV, g_partV);
    cudaGetSymbolAddress((void**)&partI, g_partI);

    int nsm = 148;
    cudaDeviceGetAttribute(&nsm, cudaDevAttrMultiProcessorCount, 0);
    int gdec = nsm;
    if (gdec > MAXGRID) gdec = MAXGRID;
    if (gdec < 128) gdec = 128;  // phases require >=128; all GB300 parts have >=148 SMs

    static int smem_set = 0;
    cudaFuncSetAttribute(dec_persist, cudaFuncAttributeMaxDynamicSharedMemorySize,
                         DEC_SMEM_FLOATS * 4);
    (void)smem_set;

    init_kernel<<<128, 256>>>(hT0, cT);

    // xproj = emb[source] @ enc_Wih^T + (bih + bhh)
    gemm_nt<true><<<dim3(GATES / 64, (LSRC * BATCH) / 64), 256>>>(
        enc_emb, src, enc_Wih, enc_bih, enc_bhh, xproj, LSRC * BATCH, GATES, HID);

    // persistent encoder recurrence (final h in hT0, c in cT)
    enc_persist<<<128, 256>>>(xproj, enc_Whh, src, hT0, hT1, cT, hs);

    // hsW = hs @ W_a
    gemm_nn<<<dim3(HID / 64, (LSRC * BATCH) / 64), 256>>>(hs, W_a, hsW, LSRC * BATCH, HID, HID);

    // persistent decoder: all 32 steps
    dec_persist<<<gdec, 256, DEC_SMEM_FLOATS * 4>>>(
        dec_emb, dec_Wih, dec_Whh, dec_bih, dec_bhh,
        W_c, b_c, out_W, out_b, hsW, hs, src,
        hT0, dT0, dT1, cT, hdrow, xT, ctxT, attT, partV, partI, out);
}